// round 2
// baseline (speedup 1.0000x reference)
#include <cuda_runtime.h>
#include <cuda_bf16.h>
#include <cstdint>

#define N_NODES 20000
#define BATCH 512
#define EMBED_DIM 32
#define NUM_SAMPLES 5001
#define TD_MAX 5000.0f
#define N4 (N_NODES / 4)          // 5000 float4 per row
#define LAMBDA_BLOCKS_X ((N4 + 255) / 256)   // 20
#define CHUNK 20                  // samples per thread in rt part (256*20 >= 5001)

// Scratch (device globals; no allocation allowed)
__device__ float d_node_u[2][N_NODES];
__device__ float d_node_v[2][N_NODES];
__device__ float d_csrc[BATCH];
__device__ float d_cdst[BATCH];
__device__ float d_inv[BATCH];
__device__ float d_psi[BATCH];
__device__ float d_gb[BATCH];
__device__ float d_alpha[BATCH];
__device__ float d_wt[BATCH];
__device__ int   d_et[BATCH];

__device__ __forceinline__ float softplus_f(float x) {
    // jax.nn.softplus(x) = max(x,0) + log1p(exp(-|x|))
    float ax = fabsf(x);
    return fmaxf(x, 0.0f) + __logf(1.0f + __expf(-ax));
}

// ---------------------------------------------------------------------------
// Kernel 1: per-node projections + per-batch scalars
// ---------------------------------------------------------------------------
__global__ void __launch_bounds__(256) prep_kernel(
    const float* __restrict__ emb,
    const int*   __restrict__ assoc,
    const int*   __restrict__ src,
    const int*   __restrict__ pdst,
    const float* __restrict__ last_update,
    const float* __restrict__ cur_time,
    const int*   __restrict__ et,
    const float* __restrict__ W0,
    const float* __restrict__ b0,
    const float* __restrict__ W1,
    const float* __restrict__ b1,
    const float* __restrict__ psi,
    const float* __restrict__ alpha,
    const float* __restrict__ w_t)
{
    int gid = blockIdx.x * blockDim.x + threadIdx.x;

    if (gid < N_NODES) {
        const float4* row = (const float4*)(emb + (size_t)gid * EMBED_DIM);
        const float4* w0u = (const float4*)W0;            // W0[0:32]
        const float4* w0v = (const float4*)(W0 + 32);     // W0[32:64]
        const float4* w1u = (const float4*)W1;
        const float4* w1v = (const float4*)(W1 + 32);
        float u0 = 0.f, u1 = 0.f, v0 = 0.f, v1 = 0.f;
        #pragma unroll
        for (int q = 0; q < EMBED_DIM / 4; q++) {
            float4 r = __ldg(row + q);
            float4 a0 = __ldg(w0u + q), b0v = __ldg(w0v + q);
            float4 a1 = __ldg(w1u + q), b1v = __ldg(w1v + q);
            u0 += r.x * a0.x + r.y * a0.y + r.z * a0.z + r.w * a0.w;
            v0 += r.x * b0v.x + r.y * b0v.y + r.z * b0v.z + r.w * b0v.w;
            u1 += r.x * a1.x + r.y * a1.y + r.z * a1.z + r.w * a1.w;
            v1 += r.x * b1v.x + r.y * b1v.y + r.z * b1v.z + r.w * b1v.w;
        }
        d_node_u[0][gid] = u0;
        d_node_u[1][gid] = u1;
        d_node_v[0][gid] = v0;
        d_node_v[1][gid] = v1;
    }

    if (gid < BATCH) {
        int b = gid;
        int e = (et[b] > 0) ? 1 : 0;
        int is = assoc[src[b]];
        int id = assoc[pdst[b]];
        const float* Wu = e ? W1 : W0;
        const float* Wv = Wu + 32;
        float bb = e ? b1[0] : b0[0];
        float s = 0.f, d = 0.f;
        const float* zs = emb + (size_t)is * EMBED_DIM;
        const float* zd = emb + (size_t)id * EMBED_DIM;
        #pragma unroll
        for (int k = 0; k < EMBED_DIM; k++) {
            s += zs[k] * Wu[k];
            d += zd[k] * Wv[k];
        }
        s += bb;
        d += bb;
        float ps = psi[e], al = alpha[e], w = w_t[e];
        float tds = (cur_time[b] - last_update[is]) * (1.0f / TD_MAX);
        float tdd = (cur_time[b] - last_update[id]) * (1.0f / TD_MAX);
        d_csrc[b]  = s + al * __expf(-w * tds);
        d_cdst[b]  = d + al * __expf(-w * tdd);
        d_inv[b]   = 1.0f / (ps + 1e-7f);
        d_psi[b]   = ps;
        d_gb[b]    = s + d - bb;   // z_src@Wu + z_dst@Wv + bias
        d_alpha[b] = al;
        d_wt[b]    = w;
        d_et[b]    = e;
    }
}

// ---------------------------------------------------------------------------
// Kernel 2 (fused): blockIdx.x < LAMBDA_BLOCKS_X -> lambda tiles (write-bound);
//                   blockIdx.x == LAMBDA_BLOCKS_X -> return_time scan for row b.
// The rt blocks are MUFU/ALU-only (one 4-byte store) so they overlap freely
// with the DRAM-write-bound lambda blocks.
// ---------------------------------------------------------------------------
__global__ void __launch_bounds__(256) fused_kernel(float* __restrict__ out)
{
    int b = blockIdx.y;
    int t = threadIdx.x;

    if (blockIdx.x < LAMBDA_BLOCKS_X) {
        // ---------------- lambda part ----------------
        int x = blockIdx.x * blockDim.x + t;   // float4 index within row
        if (x >= N4) return;

        int e = d_et[b];
        const float4* u4 = (const float4*)d_node_u[e];
        const float4* v4 = (const float4*)d_node_v[e];
        float cs  = d_csrc[b];
        float cd  = d_cdst[b];
        float inv = d_inv[b];
        float ps  = d_psi[b];

        float4 v = u4[x];       // for dst
        float4 w = v4[x];       // for src

        float4 ls, ld;
        ls.x = ps * softplus_f((cs + w.x) * inv);
        ls.y = ps * softplus_f((cs + w.y) * inv);
        ls.z = ps * softplus_f((cs + w.z) * inv);
        ls.w = ps * softplus_f((cs + w.w) * inv);
        ld.x = ps * softplus_f((cd + v.x) * inv);
        ld.y = ps * softplus_f((cd + v.y) * inv);
        ld.z = ps * softplus_f((cd + v.z) * inv);
        ld.w = ps * softplus_f((cd + v.w) * inv);

        float4* outs = (float4*)(out + (size_t)b * N_NODES);
        float4* outd = (float4*)(out + (size_t)BATCH * N_NODES + (size_t)b * N_NODES);
        outs[x] = ls;
        outd[x] = ld;
        return;
    }

    // ---------------- return_time part ----------------
    float gb  = d_gb[b];
    float al  = d_alpha[b];
    float wt  = d_wt[b];
    float inv = d_inv[b];
    float ps  = d_psi[b];

    int i0 = t * CHUNK;
    float loc[CHUNK];
    float s = 0.f;
    #pragma unroll
    for (int k = 0; k < CHUNK; k++) {
        int i = i0 + k;
        float inten = 0.f;
        if (i < NUM_SAMPLES) {
            float td = (float)i * (1.0f / TD_MAX);
            float g = gb + al * __expf(-wt * td);
            inten = ps * softplus_f(g * inv);
        }
        loc[k] = inten;
        s += inten;
    }

    // Block exclusive scan of per-thread sums
    unsigned m = 0xffffffffu;
    float v = s;
    #pragma unroll
    for (int o = 1; o < 32; o <<= 1) {
        float n = __shfl_up_sync(m, v, o);
        if ((t & 31) >= o) v += n;
    }
    __shared__ float wsum[8];
    if ((t & 31) == 31) wsum[t >> 5] = v;
    __syncthreads();
    if (t < 8) {
        float w = wsum[t];
        #pragma unroll
        for (int o = 1; o < 8; o <<= 1) {
            float n = __shfl_up_sync(0xffu, w, o);
            if (t >= o) w += n;
        }
        wsum[t] = w;
    }
    __syncthreads();
    float excl = (v - s) + ((t >= 32) ? wsum[(t >> 5) - 1] : 0.f);

    // inclusive cumsum => integral; density; weighted trapezoid
    float run = excl;
    float acc = 0.f;
    #pragma unroll
    for (int k = 0; k < CHUNK; k++) {
        int i = i0 + k;
        if (i < NUM_SAMPLES) {
            run += loc[k];                       // integral_i (TIMESTEP = 1)
            float dens = loc[k] * __expf(-run);
            float wgt = (i == NUM_SAMPLES - 1) ? 0.5f : 1.0f;  // i==0 term is 0 (t=0)
            acc += wgt * (float)i * dens;
        }
    }

    // Block reduce acc
    #pragma unroll
    for (int o = 16; o > 0; o >>= 1) acc += __shfl_down_sync(m, acc, o);
    __shared__ float rsum[8];
    if ((t & 31) == 0) rsum[t >> 5] = acc;
    __syncthreads();
    if (t == 0) {
        float tot = 0.f;
        #pragma unroll
        for (int wgrp = 0; wgrp < 8; wgrp++) tot += rsum[wgrp];
        out[(size_t)2 * BATCH * N_NODES + b] = tot;
    }
}

// ---------------------------------------------------------------------------
extern "C" void kernel_launch(void* const* d_in, const int* in_sizes, int n_in,
                              void* d_out, int out_size)
{
    // Input order (per setup_inputs dict):
    // 0 all_embeddings f32 (N,D)   1 assoc i32 (N)   2 src i32 (B)
    // 3 pos_dst i32 (B)            4 neg_dst i32 (B) 5 last_update f32 (N)
    // 6 cur_time f32 (B)           7 et i32 (B)      8 W0 f32 (1,64)
    // 9 b0 f32 (1)                 10 W1 f32 (1,64)  11 b1 f32 (1)
    // 12 psi f32 (2)               13 alpha f32 (2)  14 w_t f32 (2)
    const float* emb   = (const float*)d_in[0];
    const int*   assoc = (const int*)  d_in[1];
    const int*   src   = (const int*)  d_in[2];
    const int*   pdst  = (const int*)  d_in[3];
    const float* lu    = (const float*)d_in[5];
    const float* ct    = (const float*)d_in[6];
    const int*   et    = (const int*)  d_in[7];
    const float* W0    = (const float*)d_in[8];
    const float* b0    = (const float*)d_in[9];
    const float* W1    = (const float*)d_in[10];
    const float* b1    = (const float*)d_in[11];
    const float* psi   = (const float*)d_in[12];
    const float* alpha = (const float*)d_in[13];
    const float* w_t   = (const float*)d_in[14];
    float* out = (float*)d_out;

    prep_kernel<<<(N_NODES + 255) / 256, 256>>>(emb, assoc, src, pdst, lu, ct, et,
                                                W0, b0, W1, b1, psi, alpha, w_t);

    dim3 grid(LAMBDA_BLOCKS_X + 1, BATCH);   // +1 column of rt blocks
    fused_kernel<<<grid, 256>>>(out);
}

// round 3
// speedup vs baseline: 1.0501x; 1.0501x over previous
#include <cuda_runtime.h>
#include <cuda_bf16.h>
#include <cstdint>

#define N_NODES 20000
#define BATCH 512
#define EMBED_DIM 32
#define NUM_SAMPLES 5001
#define TD_MAX 5000.0f
#define N4 (N_NODES / 4)                     // 5000 float4 per row
#define LAMBDA_BLOCKS_X ((N4 + 255) / 256)   // 20
#define CHUNK 20                             // 256*20 >= 5001

#define L2E 1.4426950408889634f
#define LN2 0.6931471805599453f

// Scratch (device globals; no allocation allowed)
__device__ float d_node_u[2][N_NODES];
__device__ float d_node_v[2][N_NODES];
__device__ float4 d_bp0[BATCH];   // (cs*inv, cd*inv, inv, ps)
__device__ float4 d_bp1[BATCH];   // (gb*inv, alpha*inv, wt*L2E/TD_MAX, ps)
__device__ int    d_et[BATCH];

// ps * softplus(x), with psln2 = ps*ln2 prefolded.
// softplus(x) = max(x,0) + log2(1 + exp2(-|x|*log2e)) * ln2
__device__ __forceinline__ float sp_scaled(float x, float ps, float psln2) {
    float e  = exp2f(-L2E * fabsf(x));          // FMUL + EX2
    float lg = __log2f(1.0f + e);               // FADD + LG2
    return fmaf(lg, psln2, ps * fmaxf(x, 0.0f)); // FMAX + FMUL + FFMA
}

// ---------------------------------------------------------------------------
// Kernel 1: per-node projections (2 threads per node: one per e) + batch scalars
// ---------------------------------------------------------------------------
__global__ void __launch_bounds__(256) prep_kernel(
    const float* __restrict__ emb,
    const int*   __restrict__ assoc,
    const int*   __restrict__ src,
    const int*   __restrict__ pdst,
    const float* __restrict__ last_update,
    const float* __restrict__ cur_time,
    const int*   __restrict__ et,
    const float* __restrict__ W0,
    const float* __restrict__ b0,
    const float* __restrict__ W1,
    const float* __restrict__ b1,
    const float* __restrict__ psi,
    const float* __restrict__ alpha,
    const float* __restrict__ w_t)
{
    int gid = blockIdx.x * blockDim.x + threadIdx.x;

    // Projections: gid in [0, 2*N_NODES): e = gid & 1, node = gid >> 1
    if (gid < 2 * N_NODES) {
        int e = gid & 1;
        int n = gid >> 1;
        const float4* row = (const float4*)(emb + (size_t)n * EMBED_DIM);
        const float*  W   = e ? W1 : W0;
        const float4* wu  = (const float4*)W;          // [0:32]
        const float4* wv  = (const float4*)(W + 32);   // [32:64]
        float u = 0.f, v = 0.f;
        #pragma unroll
        for (int q = 0; q < EMBED_DIM / 4; q++) {
            float4 r  = __ldg(row + q);
            float4 au = __ldg(wu + q);
            float4 av = __ldg(wv + q);
            u = fmaf(r.x, au.x, fmaf(r.y, au.y, fmaf(r.z, au.z, fmaf(r.w, au.w, u))));
            v = fmaf(r.x, av.x, fmaf(r.y, av.y, fmaf(r.z, av.z, fmaf(r.w, av.w, v))));
        }
        d_node_u[e][n] = u;
        d_node_v[e][n] = v;
    }

    // Batch scalars: reuse first BATCH threads
    if (gid < BATCH) {
        int b = gid;
        int e = (et[b] > 0) ? 1 : 0;
        int is = assoc[src[b]];
        int id = assoc[pdst[b]];
        const float* Wu = e ? W1 : W0;
        const float* Wv = Wu + 32;
        float bb = e ? b1[0] : b0[0];
        float s = 0.f, d = 0.f;
        const float* zs = emb + (size_t)is * EMBED_DIM;
        const float* zd = emb + (size_t)id * EMBED_DIM;
        #pragma unroll
        for (int k = 0; k < EMBED_DIM; k++) {
            s = fmaf(zs[k], Wu[k], s);
            d = fmaf(zd[k], Wv[k], d);
        }
        s += bb;
        d += bb;
        float ps = psi[e], al = alpha[e], w = w_t[e];
        float inv = 1.0f / (ps + 1e-7f);
        float tds = (cur_time[b] - last_update[is]) * (1.0f / TD_MAX);
        float tdd = (cur_time[b] - last_update[id]) * (1.0f / TD_MAX);
        float cs = s + al * __expf(-w * tds);
        float cd = d + al * __expf(-w * tdd);
        float gb = s + d - bb;

        d_bp0[b] = make_float4(cs * inv, cd * inv, inv, ps);
        d_bp1[b] = make_float4(gb * inv, al * inv, w * (L2E / TD_MAX), ps);
        d_et[b]  = e;
    }
}

// ---------------------------------------------------------------------------
// Kernel 2 (fused): x < 20 -> lambda tile; x == 20 -> return_time scan
// ---------------------------------------------------------------------------
__global__ void __launch_bounds__(256) fused_kernel(float* __restrict__ out)
{
    int b = blockIdx.y;
    int t = threadIdx.x;

    if (blockIdx.x < LAMBDA_BLOCKS_X) {
        int x = blockIdx.x * 256 + t;   // float4 index within row
        if (x >= N4) return;

        float4 bp = d_bp0[b];           // cs_i, cd_i, inv, ps
        int e = d_et[b];
        const float4* u4 = (const float4*)d_node_u[e];
        const float4* v4 = (const float4*)d_node_v[e];
        float inv   = bp.z;
        float ps    = bp.w;
        float psln2 = ps * LN2;

        float4 v = u4[x];   // dst path uses node_u
        float4 w = v4[x];   // src path uses node_v

        float4 ls, ld;
        ls.x = sp_scaled(fmaf(w.x, inv, bp.x), ps, psln2);
        ls.y = sp_scaled(fmaf(w.y, inv, bp.x), ps, psln2);
        ls.z = sp_scaled(fmaf(w.z, inv, bp.x), ps, psln2);
        ls.w = sp_scaled(fmaf(w.w, inv, bp.x), ps, psln2);
        ld.x = sp_scaled(fmaf(v.x, inv, bp.y), ps, psln2);
        ld.y = sp_scaled(fmaf(v.y, inv, bp.y), ps, psln2);
        ld.z = sp_scaled(fmaf(v.z, inv, bp.y), ps, psln2);
        ld.w = sp_scaled(fmaf(v.w, inv, bp.y), ps, psln2);

        float4* outs = (float4*)(out + (size_t)b * N_NODES);
        float4* outd = (float4*)(out + (size_t)BATCH * N_NODES + (size_t)b * N_NODES);
        outs[x] = ls;
        outd[x] = ld;
        return;
    }

    // ---------------- return_time scan ----------------
    float4 bp = d_bp1[b];       // gbi, ali, wtn, ps
    float gbi = bp.x, ali = bp.y, wtn = bp.z, ps = bp.w;
    float psln2 = ps * LN2;

    int i0 = t * CHUNK;
    float loc[CHUNK];
    float s = 0.f;
    #pragma unroll
    for (int k = 0; k < CHUNK; k++) {
        int i = i0 + k;
        float inten = 0.f;
        if (i < NUM_SAMPLES) {
            float exc = exp2f(-wtn * (float)i);
            float x = fmaf(exc, ali, gbi);
            inten = sp_scaled(x, ps, psln2);
        }
        loc[k] = inten;
        s += inten;
    }

    // Block exclusive scan of per-thread sums
    unsigned m = 0xffffffffu;
    float v = s;
    #pragma unroll
    for (int o = 1; o < 32; o <<= 1) {
        float n = __shfl_up_sync(m, v, o);
        if ((t & 31) >= o) v += n;
    }
    __shared__ float wsum[8];
    if ((t & 31) == 31) wsum[t >> 5] = v;
    __syncthreads();
    if (t < 8) {
        float w = wsum[t];
        #pragma unroll
        for (int o = 1; o < 8; o <<= 1) {
            float n = __shfl_up_sync(0xffu, w, o);
            if (t >= o) w += n;
        }
        wsum[t] = w;
    }
    __syncthreads();
    float excl = (v - s) + ((t >= 32) ? wsum[(t >> 5) - 1] : 0.f);

    // inclusive cumsum -> integral; density; weighted trapezoid
    float run = excl;
    float acc = 0.f;
    #pragma unroll
    for (int k = 0; k < CHUNK; k++) {
        int i = i0 + k;
        if (i < NUM_SAMPLES) {
            run += loc[k];                        // integral_i (TIMESTEP = 1)
            float dens = loc[k] * exp2f(-L2E * run);
            float wgt = (i == NUM_SAMPLES - 1) ? 0.5f : 1.0f;  // i==0 term is 0
            acc = fmaf(wgt * (float)i, dens, acc);
        }
    }

    // Block reduce acc
    #pragma unroll
    for (int o = 16; o > 0; o >>= 1) acc += __shfl_down_sync(m, acc, o);
    __shared__ float rsum[8];
    if ((t & 31) == 0) rsum[t >> 5] = acc;
    __syncthreads();
    if (t == 0) {
        float tot = 0.f;
        #pragma unroll
        for (int wgrp = 0; wgrp < 8; wgrp++) tot += rsum[wgrp];
        out[(size_t)2 * BATCH * N_NODES + b] = tot;
    }
}

// ---------------------------------------------------------------------------
extern "C" void kernel_launch(void* const* d_in, const int* in_sizes, int n_in,
                              void* d_out, int out_size)
{
    const float* emb   = (const float*)d_in[0];
    const int*   assoc = (const int*)  d_in[1];
    const int*   src   = (const int*)  d_in[2];
    const int*   pdst  = (const int*)  d_in[3];
    const float* lu    = (const float*)d_in[5];
    const float* ct    = (const float*)d_in[6];
    const int*   et    = (const int*)  d_in[7];
    const float* W0    = (const float*)d_in[8];
    const float* b0    = (const float*)d_in[9];
    const float* W1    = (const float*)d_in[10];
    const float* b1    = (const float*)d_in[11];
    const float* psi   = (const float*)d_in[12];
    const float* alpha = (const float*)d_in[13];
    const float* w_t   = (const float*)d_in[14];
    float* out = (float*)d_out;

    prep_kernel<<<(2 * N_NODES + 255) / 256, 256>>>(emb, assoc, src, pdst, lu, ct, et,
                                                    W0, b0, W1, b1, psi, alpha, w_t);

    dim3 grid(LAMBDA_BLOCKS_X + 1, BATCH);   // +1 column of rt blocks
    fused_kernel<<<grid, 256>>>(out);
}